// round 11
// baseline (speedup 1.0000x reference)
#include <cuda_runtime.h>

// FEDformer FourierBlock + out-projection + residual + series decomposition.
// R12 (= R11 re-bench after infra timeout): 4-kernel pipeline.
//  k1 precomp: M[n][m] = (2/L) Wo * (W1+iW2)[n,m] * Wq   (per (n,m) block)
//  k2 dft:     Xf[b,n,m,:] = 3-mode DFT of x (direct LDG, register twiddles)
//  k3 mix:     P = M * Xf   (block per (n,m), warp per batch -> M read 1x/node)
//  k4 invavg:  xr = x + Re(sum P e^{iwt}) + bo ; out = xr - movavg(xr)

#define NNODES 2000
#define LSEQ   96
#define DM     32
#define HH     4
#define EE     8
#define MM     3
#define KAVG   25
#define PAD    12
#define TPB    128
#define MAXB   8

static __device__ float2 g_A[(size_t)NNODES * MM * DM * DM];       // 49.2 MB
static __device__ float2 g_X[(size_t)MAXB * NNODES * MM * DM];     // 12.3 MB
static __device__ float2 g_P[(size_t)MAXB * NNODES * MM * DM];     // 12.3 MB

// ---------------- k1: per-(n,m) weight fusion (math as R5, verified) -------
__global__ __launch_bounds__(TPB) void precomp_kernel(
    const float* __restrict__ Wq,
    const float* __restrict__ Wo,
    const float* __restrict__ W1,
    const float* __restrict__ W2)
{
    const int bid = blockIdx.x;           // bid = n*3 + m
    const int n = bid / MM, m = bid - n * MM;
    const int tid = threadIdx.x;
    const float scale = 2.0f / (float)LSEQ;

    __shared__ float sWq[DM*DM], sWo[DM*DM];
    __shared__ float s1[HH*EE*EE], s2[HH*EE*EE];     // mode-m slice (256 each)
    __shared__ float B1[DM*33], B2[DM*33];           // [ho][din], pad 33

    {
        const float4* qg = (const float4*)Wq;
        const float4* og = (const float4*)Wo;
        float4* q4 = (float4*)sWq;  float4* o4 = (float4*)sWo;
        #pragma unroll
        for (int i = tid; i < (DM*DM)/4; i += TPB) { q4[i] = qg[i]; o4[i] = og[i]; }
        const float* w1g = W1 + (size_t)n * (HH*EE*EE*MM);
        const float* w2g = W2 + (size_t)n * (HH*EE*EE*MM);
        #pragma unroll
        for (int i = tid; i < HH*EE*EE; i += TPB) {
            s1[i] = w1g[i*MM + m];
            s2[i] = w2g[i*MM + m];
        }
    }
    __syncthreads();

    // B[ho][din] = sum_e W{1,2}[h][e][o] * Wq[h*8+e][din]
    #pragma unroll
    for (int idx = tid; idx < DM*DM; idx += TPB) {
        const int ho = idx >> 5, din = idx & 31;
        const int h = ho >> 3, o = ho & 7;
        float a1 = 0.f, a2 = 0.f;
        #pragma unroll
        for (int e = 0; e < EE; ++e) {
            const float wq = sWq[(h*8 + e)*DM + din];
            const int wi = (h*EE + e)*EE + o;
            a1 = fmaf(s1[wi], wq, a1);
            a2 = fmaf(s2[wi], wq, a2);
        }
        B1[ho*33 + din] = a1;
        B2[ho*33 + din] = a2;
    }
    __syncthreads();

    // M[dout][din] = sum_ho Wo[dout][ho] * B[ho][din]; store [din][dout]
    #pragma unroll
    for (int idx = tid; idx < DM*DM; idx += TPB) {
        const int din = idx >> 5, dout = idx & 31;
        float mr = 0.f, mi = 0.f;
        #pragma unroll 8
        for (int k = 0; k < DM; ++k) {
            const int ho = (dout + k) & 31;          // conflict-free rotation
            const float wo = sWo[dout*DM + ho];
            mr = fmaf(wo, B1[ho*33 + din], mr);
            mi = fmaf(wo, B2[ho*33 + din], mi);
        }
        g_A[(size_t)bid*(DM*DM) + din*DM + dout] = make_float2(mr*scale, mi*scale);
    }
}

// ---------------- k2: forward 3-mode DFT -----------------------------------
__global__ __launch_bounds__(TPB, 6) void dft_kernel(const float* __restrict__ x)
{
    const int tid  = threadIdx.x;
    const int w    = tid >> 5;
    const int lane = tid & 31;
    const size_t bid = blockIdx.x;                   // = b*NNODES + n (b-major)
    const float* xg = x + bid * (LSEQ*DM) + (size_t)(w*24) * DM + lane;

    __shared__ float spart[4*6*32];

    float pc1, ps1, pc4, ps4, pc5, ps5;
    sincospif(1.0f/48.0f, &ps1, &pc1);
    sincospif(4.0f/48.0f, &ps4, &pc4);
    sincospif(5.0f/48.0f, &ps5, &pc5);
    const float c0 = (w == 0) ? 1.f : (w == 2 ? -1.f : 0.f);
    const float s0 = (w == 1) ? 1.f : (w == 3 ? -1.f : 0.f);

    {
        float c1 = c0, s1 = s0, c4 = 1.f, s4 = 0.f, c5 = c0, s5 = s0;
        float ar1=0.f, ai1=0.f, ar2=0.f, ai2=0.f, ar3=0.f, ai3=0.f;
        #pragma unroll
        for (int i = 0; i < 24; ++i) {
            const float v = xg[i * DM];
            ar1 = fmaf(v, c1, ar1);  ai1 = fmaf(v, s1, ai1);
            ar2 = fmaf(v, c4, ar2);  ai2 = fmaf(v, s4, ai2);
            ar3 = fmaf(v, c5, ar3);  ai3 = fmaf(v, s5, ai3);
            float nc, ns;
            nc = fmaf(c1, pc1, -s1*ps1); ns = fmaf(s1, pc1, c1*ps1); c1 = nc; s1 = ns;
            nc = fmaf(c4, pc4, -s4*ps4); ns = fmaf(s4, pc4, c4*ps4); c4 = nc; s4 = ns;
            nc = fmaf(c5, pc5, -s5*ps5); ns = fmaf(s5, pc5, c5*ps5); c5 = nc; s5 = ns;
        }
        spart[(w*6 + 0)*32 + lane] = ar1;  spart[(w*6 + 1)*32 + lane] = ai1;
        spart[(w*6 + 2)*32 + lane] = ar2;  spart[(w*6 + 3)*32 + lane] = ai2;
        spart[(w*6 + 4)*32 + lane] = ar3;  spart[(w*6 + 5)*32 + lane] = ai3;
    }
    __syncthreads();

    if (w < 3) {
        const int m = w, j = lane;
        float fr = 0.f, fi = 0.f;
        #pragma unroll
        for (int ww = 0; ww < 4; ++ww) {
            fr += spart[(ww*6 + 2*m + 0)*32 + j];
            fi += spart[(ww*6 + 2*m + 1)*32 + j];
        }
        g_X[(bid*MM + m)*DM + j] = make_float2(fr, -fi);   // Xf = sum x (cos - i sin)
    }
}

// ---------------- k3: P = M * Xf (block per (n,m), warp per batch) ---------
__global__ __launch_bounds__(256) void mix_kernel(int B)
{
    const int bid = blockIdx.x;                      // = n*3 + m
    const int n = bid / MM;                          // m = bid % MM (implicit)
    const int b = threadIdx.x >> 5;                  // warp = batch element
    const int j = threadIdx.x & 31;

    __shared__ float sXr[MAXB][DM], sXi[MAXB][DM];

    if (b < B) {
        const size_t xoff = (((size_t)b*NNODES + n)*MM + (bid - n*MM))*DM;
        const float2 xv = g_X[xoff + j];
        sXr[b][j] = xv.x;  sXi[b][j] = xv.y;
        __syncwarp();
        const float2* __restrict__ Am = g_A + (size_t)bid*(DM*DM);
        float pr = 0.f, pi = 0.f;
        #pragma unroll 8
        for (int d = 0; d < DM; ++d) {
            const float2 a = __ldg(&Am[d*DM + j]);   // coalesced, L1-hot across warps
            const float xr = sXr[b][d];              // broadcast
            const float xi = sXi[b][d];
            pr = fmaf(a.x, xr, fmaf(-a.y, xi, pr));
            pi = fmaf(a.x, xi, fmaf( a.y, xr, pi));
        }
        g_P[xoff + j] = make_float2(pr, pi);
    }
}

// ---------------- k4: inverse transform + residual + decomposition --------
__global__ __launch_bounds__(TPB, 6) void invavg_kernel(
    const float* __restrict__ x,
    const float* __restrict__ bo,
    float* __restrict__ out)
{
    const int tid  = threadIdx.x;
    const int w    = tid >> 5;
    const int lane = tid & 31;
    const size_t bid = blockIdx.x;                   // = b*NNODES + n
    const size_t base = bid * (LSEQ*DM);
    const int t0 = w * 24;
    const float* xg = x + base + (size_t)t0 * DM + lane;

    __shared__ float sxr[LSEQ * DM];

    float pc1, ps1, pc4, ps4, pc5, ps5;
    sincospif(1.0f/48.0f, &ps1, &pc1);
    sincospif(4.0f/48.0f, &ps4, &pc4);
    sincospif(5.0f/48.0f, &ps5, &pc5);
    const float c0 = (w == 0) ? 1.f : (w == 2 ? -1.f : 0.f);
    const float s0 = (w == 1) ? 1.f : (w == 3 ? -1.f : 0.f);

    const float2 P0 = __ldg(&g_P[(bid*MM + 0)*DM + lane]);
    const float2 P1 = __ldg(&g_P[(bid*MM + 1)*DM + lane]);
    const float2 P2 = __ldg(&g_P[(bid*MM + 2)*DM + lane]);
    const float bod = __ldg(bo + lane);

    float r[24];
    {
        float c1 = c0, s1 = s0, c4 = 1.f, s4 = 0.f, c5 = c0, s5 = s0;
        #pragma unroll
        for (int i = 0; i < 24; ++i) {
            float acc = bod;
            acc = fmaf(P0.x, c1, acc); acc = fmaf(-P0.y, s1, acc);
            acc = fmaf(P1.x, c4, acc); acc = fmaf(-P1.y, s4, acc);
            acc = fmaf(P2.x, c5, acc); acc = fmaf(-P2.y, s5, acc);
            r[i] = xg[i * DM] + acc;
            sxr[(t0 + i)*DM + lane] = r[i];
            float nc, ns;
            nc = fmaf(c1, pc1, -s1*ps1); ns = fmaf(s1, pc1, c1*ps1); c1 = nc; s1 = ns;
            nc = fmaf(c4, pc4, -s4*ps4); ns = fmaf(s4, pc4, c4*ps4); c4 = nc; s4 = ns;
            nc = fmaf(c5, pc5, -s5*ps5); ns = fmaf(s5, pc5, c5*ps5); c5 = nc; s5 = ns;
        }
    }
    __syncthreads();

    {
        float win = 0.f;
        #pragma unroll
        for (int j = 0; j <= 12; ++j) win += r[j];
        if (w == 0) {
            win += 12.f * r[0];
        } else {
            #pragma unroll
            for (int j = 1; j <= 12; ++j) win += sxr[(t0 - j)*DM + lane];
        }
        float* og = out + base + (size_t)t0 * DM + lane;
        #pragma unroll
        for (int i = 0; i < 24; ++i) {
            og[i * DM] = r[i] - win * (1.0f/(float)KAVG);
            float vhi, vlo;
            if (i + 13 < 24)      vhi = r[i + 13];
            else if (w == 3)      vhi = r[23];
            else                  vhi = sxr[(t0 + i + 13)*DM + lane];
            if (i >= 12)          vlo = r[i - 12];
            else if (w == 0)      vlo = r[0];
            else                  vlo = sxr[(t0 + i - 12)*DM + lane];
            win += vhi - vlo;
        }
    }
}

extern "C" void kernel_launch(void* const* d_in, const int* in_sizes, int n_in,
                              void* d_out, int out_size) {
    // metadata order: x, Wq, bq, Wk, bk, Wv, bv, Wo, bo, W1, W2
    const float* x  = (const float*)d_in[0];
    const float* Wq = (const float*)d_in[1];
    const float* Wo = (const float*)d_in[7];
    const float* bo = (const float*)d_in[8];
    const float* W1 = (const float*)d_in[9];
    const float* W2 = (const float*)d_in[10];
    float* out = (float*)d_out;

    const int B = in_sizes[0] / (NNODES * LSEQ * DM);

    precomp_kernel<<<NNODES * MM, TPB>>>(Wq, Wo, W1, W2);
    dft_kernel   <<<NNODES * B, TPB>>>(x);
    mix_kernel   <<<NNODES * MM, 256>>>(B);
    invavg_kernel<<<NNODES * B, TPB>>>(x, bo, out);
}